// round 9
// baseline (speedup 1.0000x reference)
#include <cuda_runtime.h>
#include <cuda_bf16.h>
#include <cstdint>

// Problem constants (TemporalGNNModel_515396076301)
#define NN 20000
#define EE 640000

typedef unsigned long long ull;

// ---------------- device scratch (static: no allocations allowed) -------------
__device__ int   g_is64;
__device__ int   g_cnt[NN];
__device__ int   g_cursor[NN];
__device__ int   g_rowptr[NN + 1];
__device__ float g_dinv[NN];
__device__ int2  g_edge[EE];         // (src col, norm weight as float bits)
__device__ float g_hbuf[64000000];   // [T,N,H]  x @ gcn_w
__device__ float g_seq[64000000];    // [T,N,H]  GCN output sequence

// ---------------- helpers ----------------------------------------------------
__device__ __forceinline__ int edge_at(const void* e, long long idx) {
    if (g_is64) return (int)((const long long*)e)[idx];
    return ((const int*)e)[idx];
}
__device__ __forceinline__ float sigf(float x) {
    return __fdividef(1.0f, 1.0f + __expf(-x));
}
__device__ __forceinline__ float tanh_fast(float x) {
    return 2.0f * sigf(2.0f * x) - 1.0f;
}
__device__ __forceinline__ uint32_t smem_u32(const void* p) {
    uint32_t a;
    asm("{ .reg .u64 t; cvta.to.shared.u64 t, %1; cvt.u32.u64 %0, t; }"
        : "=r"(a) : "l"(p));
    return a;
}

// ---- packed f32x2 helpers (k_transform) --------------------------------------
__device__ __forceinline__ ull fma2(ull a, ull b, ull c) {
    ull d;
    asm("fma.rn.f32x2 %0, %1, %2, %3;" : "=l"(d) : "l"(a), "l"(b), "l"(c));
    return d;
}
__device__ __forceinline__ ull dup2(float a) {
    ull r; unsigned u = __float_as_uint(a);
    asm("mov.b64 %0, {%1, %1};" : "=l"(r) : "r"(u));
    return r;
}
__device__ __forceinline__ void unpack2(ull v, float& x, float& y) {
    unsigned lo, hi;
    asm("mov.b64 {%0, %1}, %2;" : "=r"(lo), "=r"(hi) : "l"(v));
    x = __uint_as_float(lo); y = __uint_as_float(hi);
}

// ---------------- K0..K4: CSR build ------------------------------------------
__global__ void k_init(const void* e, int N) {
    int i = blockIdx.x * blockDim.x + threadIdx.x;
    if (i < N) { g_cnt[i] = 0; g_cursor[i] = 0; }
    if (i == 0) {
        const unsigned long long* p = (const unsigned long long*)e;
        int is64 = 1;
        for (int k = 0; k < 64; k++)
            if (p[k] >= (unsigned long long)N) { is64 = 0; break; }
        g_is64 = is64;
    }
}
__global__ void k_count(const void* e, int E) {
    int i = blockIdx.x * blockDim.x + threadIdx.x;
    if (i >= E) return;
    atomicAdd(&g_cnt[edge_at(e, (long long)E + i)], 1);
}
__global__ void k_dinv(int N) {
    int i = blockIdx.x * blockDim.x + threadIdx.x;
    if (i >= N) return;
    g_dinv[i] = rsqrtf((float)(g_cnt[i] + 1));
}
__global__ void k_scan(int N) {
    __shared__ int wsum[32];
    int tid = threadIdx.x;
    int chunk = (N + 1023) >> 10;
    int lo = tid * chunk, hi = min(lo + chunk, N);
    int s = 0;
    for (int i = lo; i < hi; i++) s += g_cnt[i];
    int l = tid & 31, w = tid >> 5;
    int inc = s;
#pragma unroll
    for (int o = 1; o < 32; o <<= 1) {
        int v = __shfl_up_sync(0xffffffffu, inc, o);
        if (l >= o) inc += v;
    }
    if (l == 31) wsum[w] = inc;
    __syncthreads();
    if (w == 0) {
        int v = wsum[l], iv = v;
#pragma unroll
        for (int o = 1; o < 32; o <<= 1) {
            int u = __shfl_up_sync(0xffffffffu, iv, o);
            if (l >= o) iv += u;
        }
        wsum[l] = iv - v;
    }
    __syncthreads();
    int run = wsum[w] + (inc - s);
    for (int i = lo; i < hi; i++) { g_rowptr[i] = run; run += g_cnt[i]; }
    if (hi == N) g_rowptr[N] = run;
}
__global__ void k_fill(const void* e, int E) {
    int i = blockIdx.x * blockDim.x + threadIdx.x;
    if (i >= E) return;
    int s = edge_at(e, i);
    int d = edge_at(e, (long long)E + i);
    int slot = g_rowptr[d] + atomicAdd(&g_cursor[d], 1);
    g_edge[slot] = make_int2(s, __float_as_int(g_dinv[s] * g_dinv[d]));
}

// ---------------- K5: transform ------------------------------------------------
__global__ void k_transform(const float* __restrict__ x,
                            const float* __restrict__ W, int R) {
    extern __shared__ float sm[];
    float* Xs = sm;
    float* Ws = sm + 128 * 64;
    int t = threadIdx.x;
    long long r0 = (long long)blockIdx.x * 128;
    for (int i = t; i < 64 * 64; i += 256) Ws[i] = W[i];
    for (int i = t; i < 128 * 16; i += 256) {
        int row = i >> 4, q = i & 15;
        float4 v = make_float4(0.f, 0.f, 0.f, 0.f);
        if (r0 + row < R) v = ((const float4*)x)[(r0 + row) * 16 + q];
        *(float4*)&Xs[row * 64 + q * 4] = v;
    }
    __syncthreads();
    int tx = t & 15, ty = t >> 4;
    ull acc2[8][2];
#pragma unroll
    for (int i = 0; i < 8; i++) { acc2[i][0] = 0; acc2[i][1] = 0; }
#pragma unroll 8
    for (int k = 0; k < 64; k++) {
        const ull* wp = (const ull*)&Ws[k * 64 + tx * 4];
        ull w2a = wp[0], w2b = wp[1];
#pragma unroll
        for (int i = 0; i < 8; i++) {
            ull a2 = dup2(Xs[(ty * 8 + i) * 64 + k]);
            acc2[i][0] = fma2(w2a, a2, acc2[i][0]);
            acc2[i][1] = fma2(w2b, a2, acc2[i][1]);
        }
    }
#pragma unroll
    for (int i = 0; i < 8; i++) {
        long long row = r0 + ty * 8 + i;
        if (row < R) {
            float4 v;
            unpack2(acc2[i][0], v.x, v.y);
            unpack2(acc2[i][1], v.z, v.w);
            *(float4*)&g_hbuf[row * 64 + tx * 4] = v;
        }
    }
}

// ---------------- K6: aggregate ------------------------------------------------
__global__ void k_agg(const float* __restrict__ gcn_b, int N, int nbd) {
    int t = blockIdx.x / nbd;
    int dst = ((blockIdx.x % nbd) << 3) + (threadIdx.x >> 5);
    if (dst >= N) return;
    int l = threadIdx.x & 31;
    const float2* hb = (const float2*)g_hbuf;
    long long tbase = (long long)t * N;
    float dv = g_dinv[dst];
    float2 acc;
    {
        float2 v = hb[(tbase + dst) * 32 + l];
        float sw = dv * dv;
        acc.x = sw * v.x; acc.y = sw * v.y;
    }
    int e = g_rowptr[dst], e1 = g_rowptr[dst + 1];
    for (; e + 4 <= e1; e += 4) {
        int2 p0 = g_edge[e], p1 = g_edge[e + 1], p2 = g_edge[e + 2], p3 = g_edge[e + 3];
        float2 v0 = hb[(tbase + p0.x) * 32 + l];
        float2 v1 = hb[(tbase + p1.x) * 32 + l];
        float2 v2 = hb[(tbase + p2.x) * 32 + l];
        float2 v3 = hb[(tbase + p3.x) * 32 + l];
        acc.x += __int_as_float(p0.y) * v0.x; acc.y += __int_as_float(p0.y) * v0.y;
        acc.x += __int_as_float(p1.y) * v1.x; acc.y += __int_as_float(p1.y) * v1.y;
        acc.x += __int_as_float(p2.y) * v2.x; acc.y += __int_as_float(p2.y) * v2.y;
        acc.x += __int_as_float(p3.y) * v3.x; acc.y += __int_as_float(p3.y) * v3.y;
    }
    for (; e < e1; e++) {
        int2 p = g_edge[e];
        float2 v = hb[(tbase + p.x) * 32 + l];
        acc.x += __int_as_float(p.y) * v.x; acc.y += __int_as_float(p.y) * v.y;
    }
    float2 b2 = ((const float2*)gcn_b)[l];
    float2 r;
    r.x = fmaxf(acc.x + b2.x, 0.f);
    r.y = fmaxf(acc.y + b2.y, 0.f);
    ((float2*)g_seq)[(tbase + dst) * 32 + l] = r;
}

// ---------------- K7: LSTM, mma.sync + ldmatrix + RUNTIME-PROBED D layout ------
// CTA = 80 nodes, 10 warps: wr = w%5 -> rows 16wr..+15; dg = w/5 -> gate cols
// n0 = 128dg..+127 (16 n-tiles of 8). Per step: gates[80,256] = A[80,128] @
// B[128,256], bf16 hi/lo 3-pass split. B col n = 4*dim + gate (pure index
// math). A/B loaded with ldmatrix from UNSWIZZLED padded rows. The D-fragment
// (row, col) per lane slot is DISCOVERED at startup via two probe MMAs, so no
// accumulator-layout knowledge is assumed anywhere. Epilogue round-trips each
// D tile through per-warp scratch: store by probed coords, read canonically.
#define NPC 80
#define THR 320
#define AST 272                            // A row stride bytes
#define BHS 272                            // B-hi row stride bytes
#define BLS 256                            // B-lo row stride bytes (unpadded)
#define OFF_AHI  0                         // 80*272  = 21760
#define OFF_ALO  21760
#define OFF_BHI  43520                     // 256*272 = 69632
#define OFF_BLO  113152                    // 256*256 = 65536
#define OFF_SCR  178688                    // 10 warps * 512B
#define OFF_PRB  183808                    // probe staging: A 512B + B 256B
#define OFF_BIAS 184576                    // 256 f32
#define OFF_OSM  185600                    // 80 f32 (+pad)
#define SMEM_LT  185984

__device__ __forceinline__ void ldsm_x4(uint32_t* r, uint32_t a) {
    asm volatile("ldmatrix.sync.aligned.m8n8.x4.shared.b16 {%0,%1,%2,%3}, [%4];"
                 : "=r"(r[0]), "=r"(r[1]), "=r"(r[2]), "=r"(r[3]) : "r"(a));
}
__device__ __forceinline__ void ldsm_x2(uint32_t* r, uint32_t a) {
    asm volatile("ldmatrix.sync.aligned.m8n8.x2.shared.b16 {%0,%1}, [%2];"
                 : "=r"(r[0]), "=r"(r[1]) : "r"(a));
}
__device__ __forceinline__ void mma16816(float4& d, const uint32_t a[4],
                                         uint32_t b0, uint32_t b1) {
    asm volatile(
        "mma.sync.aligned.m16n8k16.row.col.f32.bf16.bf16.f32 "
        "{%0,%1,%2,%3}, {%4,%5,%6,%7}, {%8,%9}, {%0,%1,%2,%3};"
        : "+f"(d.x), "+f"(d.y), "+f"(d.z), "+f"(d.w)
        : "r"(a[0]), "r"(a[1]), "r"(a[2]), "r"(a[3]), "r"(b0), "r"(b1));
}
__device__ __forceinline__ void pack8(const float* v, uint4& hv, uint4& lv) {
    unsigned h[8], l[8];
#pragma unroll
    for (int i = 0; i < 8; i++) {
        __nv_bfloat16 b = __float2bfloat16_rn(v[i]);
        float rem = v[i] - __bfloat162float(b);
        __nv_bfloat16 c = __float2bfloat16_rn(rem);
        h[i] = (unsigned)__bfloat16_as_ushort(b);
        l[i] = (unsigned)__bfloat16_as_ushort(c);
    }
    hv = make_uint4(h[0] | (h[1] << 16), h[2] | (h[3] << 16),
                    h[4] | (h[5] << 16), h[6] | (h[7] << 16));
    lv = make_uint4(l[0] | (l[1] << 16), l[2] | (l[3] << 16),
                    l[4] | (l[5] << 16), l[6] | (l[7] << 16));
}

__global__ __launch_bounds__(THR, 1)
void k_lstm_pb(const float* __restrict__ w_ih, const float* __restrict__ w_hh,
               const float* __restrict__ b_ih, const float* __restrict__ b_hh,
               const float* __restrict__ fc_w, const float* __restrict__ fc_b,
               float* __restrict__ out, int N, int T) {
    extern __shared__ char smc[];
    uint32_t sb = smem_u32(smc);
    float* scr     = (float*)(smc + OFF_SCR);
    float* bias_sm = (float*)(smc + OFF_BIAS);
    float* osm     = (float*)(smc + OFF_OSM);
    __nv_bfloat16* prb = (__nv_bfloat16*)(smc + OFF_PRB);

    int tid = threadIdx.x;
    int w = tid >> 5, lane = tid & 31;
    int wr = w % 5, dg = w / 5;
    int m0 = wr * 16, n0 = dg * 128;
    int base = blockIdx.x * NPC;

    // ---- B fill: col n = 4*dim + gate; source row r = (n&3)*64 + (n>>2) ----
    for (int i = tid; i < 256 * 128; i += THR) {
        int n = i >> 7, k = i & 127;
        int r = (n & 3) * 64 + (n >> 2);
        float v = (k < 64) ? w_ih[r * 64 + k] : w_hh[r * 64 + (k - 64)];
        __nv_bfloat16 hi = __float2bfloat16_rn(v);
        __nv_bfloat16 lo = __float2bfloat16_rn(v - __bfloat162float(hi));
        *(__nv_bfloat16*)(smc + OFF_BHI + n * BHS + k * 2) = hi;
        *(__nv_bfloat16*)(smc + OFF_BLO + n * BLS + k * 2) = lo;
    }
    if (tid < 256) {
        int r = (tid & 3) * 64 + (tid >> 2);
        bias_sm[tid] = b_ih[r] + b_hh[r];
    }
    if (tid < NPC) osm[tid] = 0.f;

    // ---- initial A: s(0) at k 0..63, h(0)=0 at k 64..127 ----
    int srow = tid >> 2, scg = tid & 3;   // 320 threads = 80 rows x 4 quarters
    {
        float v[16];
        int node = base + srow;
        if (node < N) {
            const float4* sp = (const float4*)(g_seq + (long long)node * 64 + scg * 16);
#pragma unroll
            for (int j = 0; j < 4; j++) *(float4*)&v[j * 4] = sp[j];
        } else {
#pragma unroll
            for (int j = 0; j < 16; j++) v[j] = 0.f;
        }
        uint4 hv, lv;
        int b0 = srow * AST + scg * 32;
        pack8(v, hv, lv);
        *(uint4*)(smc + OFF_AHI + b0)      = hv;  *(uint4*)(smc + OFF_ALO + b0)      = lv;
        pack8(v + 8, hv, lv);
        *(uint4*)(smc + OFF_AHI + b0 + 16) = hv;  *(uint4*)(smc + OFF_ALO + b0 + 16) = lv;
        uint4 z = make_uint4(0, 0, 0, 0);
        int b1 = srow * AST + 128 + scg * 32;
        *(uint4*)(smc + OFF_AHI + b1)      = z;   *(uint4*)(smc + OFF_ALO + b1)      = z;
        *(uint4*)(smc + OFF_AHI + b1 + 16) = z;   *(uint4*)(smc + OFF_ALO + b1 + 16) = z;
    }

    // ---- PROBE: discover D-fragment (row, col) per lane slot ----
    int rowIdx[4], colIdx[4];
    {
        uint32_t aaddr = sb + OFF_PRB + (lane & 15) * 32 + (lane >> 4) * 16;
        uint32_t baddr = sb + OFF_PRB + 512 + (lane & 7) * 32 + ((lane >> 3) & 1) * 16;
        float4 P;
        uint32_t a[4], b[2];
        // probe 1: A[r][0] = r, B[0][c] = 1  ->  D[r][c] = r
        for (int i = tid; i < 256; i += THR) {
            int r = i >> 4, k = i & 15;
            prb[r * 16 + k] = __float2bfloat16_rn((k == 0) ? (float)r : 0.f);
        }
        for (int i = tid; i < 128; i += THR) {
            int n = i >> 4, k = i & 15;
            prb[256 + n * 16 + k] = __float2bfloat16_rn((k == 0) ? 1.f : 0.f);
        }
        __syncthreads();
        P = make_float4(0.f, 0.f, 0.f, 0.f);
        ldsm_x4(a, aaddr); ldsm_x2(b, baddr);
        mma16816(P, a, b[0], b[1]);
        rowIdx[0] = (int)(P.x + 0.5f); rowIdx[1] = (int)(P.y + 0.5f);
        rowIdx[2] = (int)(P.z + 0.5f); rowIdx[3] = (int)(P.w + 0.5f);
        __syncthreads();
        // probe 2: A[r][0] = 1, B[0][c] = c  ->  D[r][c] = c
        for (int i = tid; i < 256; i += THR) {
            int r = i >> 4, k = i & 15;
            prb[r * 16 + k] = __float2bfloat16_rn((k == 0) ? 1.f : 0.f);
        }
        for (int i = tid; i < 128; i += THR) {
            int n = i >> 4, k = i & 15;
            prb[256 + n * 16 + k] = __float2bfloat16_rn((k == 0) ? (float)n : 0.f);
        }
        __syncthreads();
        P = make_float4(0.f, 0.f, 0.f, 0.f);
        ldsm_x4(a, aaddr); ldsm_x2(b, baddr);
        mma16816(P, a, b[0], b[1]);
        colIdx[0] = (int)(P.x + 0.5f); colIdx[1] = (int)(P.y + 0.5f);
        colIdx[2] = (int)(P.z + 0.5f); colIdx[3] = (int)(P.w + 0.5f);
    }
    // clamp into scratch bounds (garbage-safe: wrong answer, never corruption)
    int sidx[4];
#pragma unroll
    for (int s = 0; s < 4; s++)
        sidx[s] = ((rowIdx[s] & 15) * 8 + (colIdx[s] & 7));

    // ---- per-lane addresses (ldmatrix; standard lane->row grouping) ----
    uint32_t aOff = (uint32_t)(m0 + (lane & 15)) * AST + (lane >> 4) * 16;
    int bRow = n0 + 8 * ((lane >> 4) & 1) + (lane & 7);
    uint32_t kg16 = ((lane >> 3) & 1) * 16;

    float* scr_w = scr + w * 128;          // 16x8 f32 tile
    int erow = lane >> 1, dsel = lane & 1; // epilogue: cell (erow, 2nt+dsel)
    float cst[16];
#pragma unroll
    for (int i = 0; i < 16; i++) cst[i] = 0.f;
    float fcs = 0.f;

#pragma unroll 1
    for (int t = 0; t < T; t++) {
        float pf[16];
        bool hp = (t + 1) < T;
        if (hp) {
            int node = base + srow;
            if (node < N) {
                const float4* sp = (const float4*)(g_seq +
                    ((long long)(t + 1) * N + node) * 64 + scg * 16);
#pragma unroll
                for (int j = 0; j < 4; j++) *(float4*)&pf[j * 4] = sp[j];
            } else {
#pragma unroll
                for (int j = 0; j < 16; j++) pf[j] = 0.f;
            }
        }

        __syncthreads();                   // A writes from prev step visible

        float4 D[16];
#pragma unroll
        for (int q = 0; q < 16; q++) D[q] = make_float4(0.f, 0.f, 0.f, 0.f);

#pragma unroll 1
        for (int ps = 0; ps < 3; ps++) {
            uint32_t Ab = sb + ((ps == 2) ? OFF_ALO : OFF_AHI);
            int bLo = (ps == 1);
#pragma unroll 1
            for (int kc = 0; kc < 8; kc++) {
                uint32_t kb = kc * 32;
                uint32_t a[4];
                ldsm_x4(a, Ab + aOff + kb);
#pragma unroll
                for (int p = 0; p < 8; p++) {
                    uint32_t bb[4];
                    uint32_t ba = bLo
                        ? sb + OFF_BLO + (uint32_t)(bRow + 16 * p) * BLS + kb + kg16
                        : sb + OFF_BHI + (uint32_t)(bRow + 16 * p) * BHS + kb + kg16;
                    ldsm_x4(bb, ba);
                    mma16816(D[2 * p],     a, bb[0], bb[1]);
                    mma16816(D[2 * p + 1], a, bb[2], bb[3]);
                }
            }
        }

        __syncthreads();                   // all A reads done before h writes

        // ---- epilogue: per n-tile scratch round-trip via probed coords ----
#pragma unroll 1
        for (int nt = 0; nt < 16; nt++) {
            scr_w[sidx[0]] = D[nt].x;
            scr_w[sidx[1]] = D[nt].y;
            scr_w[sidx[2]] = D[nt].z;
            scr_w[sidx[3]] = D[nt].w;
            __syncwarp();
            int nb = n0 + 8 * nt;
            float iv = scr_w[erow * 8 + dsel * 4 + 0] + bias_sm[nb + dsel * 4 + 0];
            float fv = scr_w[erow * 8 + dsel * 4 + 1] + bias_sm[nb + dsel * 4 + 1];
            float gv = scr_w[erow * 8 + dsel * 4 + 2] + bias_sm[nb + dsel * 4 + 2];
            float ov = scr_w[erow * 8 + dsel * 4 + 3] + bias_sm[nb + dsel * 4 + 3];
            float c = sigf(fv) * cst[nt] + sigf(iv) * tanh_fast(gv);
            cst[nt] = c;
            float h = sigf(ov) * tanh_fast(c);
            int dim = (nb >> 2) + dsel;
            int grow = m0 + erow;
            int el = grow * AST + (64 + dim) * 2;
            __nv_bfloat16 bh = __float2bfloat16_rn(h);
            *(__nv_bfloat16*)(smc + OFF_AHI + el) = bh;
            *(__nv_bfloat16*)(smc + OFF_ALO + el) =
                __float2bfloat16_rn(h - __bfloat162float(bh));
            if (t == T - 1) fcs += h * __ldg(&fc_w[dim]);
            __syncwarp();
        }

        if (hp) {
            uint4 hv, lv;
            int b0 = srow * AST + scg * 32;
            pack8(pf, hv, lv);
            *(uint4*)(smc + OFF_AHI + b0)      = hv;  *(uint4*)(smc + OFF_ALO + b0)      = lv;
            pack8(pf + 8, hv, lv);
            *(uint4*)(smc + OFF_AHI + b0 + 16) = hv;  *(uint4*)(smc + OFF_ALO + b0 + 16) = lv;
        }
    }

    // FC: combine dim pair, then the two dim-half warps via osm atomics
    fcs += __shfl_xor_sync(0xffffffffu, fcs, 1);
    if (dsel == 0) atomicAdd(&osm[m0 + erow], fcs);

    __syncthreads();
    if (tid < NPC && base + tid < N) out[base + tid] = osm[tid] + fc_b[0];
}

// ---------------- launcher ------------------------------------------------------
extern "C" void kernel_launch(void* const* d_in, const int* in_sizes, int n_in,
                              void* d_out, int out_size) {
    const float* x     = (const float*)d_in[0];
    const void*  edges = d_in[1];
    const float* gcn_w = (const float*)d_in[2];
    const float* gcn_b = (const float*)d_in[3];
    const float* w_ih  = (const float*)d_in[4];
    const float* w_hh  = (const float*)d_in[5];
    const float* b_ih  = (const float*)d_in[6];
    const float* b_hh  = (const float*)d_in[7];
    const float* fc_w  = (const float*)d_in[8];
    const float* fc_b  = (const float*)d_in[9];
    float* out = (float*)d_out;

    int N = out_size;                 // 20000
    int E = in_sizes[1] / 2;          // 640000
    int H = in_sizes[3];              // 64
    int F = in_sizes[2] / H;          // 64
    int T = in_sizes[0] / (N * F);    // 50
    int R = T * N;

    cudaFuncSetAttribute(k_lstm_pb, cudaFuncAttributeMaxDynamicSharedMemorySize,
                         SMEM_LT);

    k_init <<<(N + 255) / 256, 256>>>(edges, N);
    k_count<<<(E + 255) / 256, 256>>>(edges, E);
    k_dinv <<<(N + 255) / 256, 256>>>(N);
    k_scan <<<1, 1024>>>(N);
    k_fill <<<(E + 255) / 256, 256>>>(edges, E);

    k_transform<<<(R + 127) / 128, 256, (128 * 64 + 64 * 64) * 4>>>(x, gcn_w, R);

    int nbd = (N + 7) >> 3;
    k_agg<<<T * nbd, 256>>>(gcn_b, N, nbd);

    k_lstm_pb<<<(N + NPC - 1) / NPC, THR, SMEM_LT>>>(
        w_ih, w_hh, b_ih, b_hh, fc_w, fc_b, out, N, T);
}

// round 10
// speedup vs baseline: 1.0018x; 1.0018x over previous
#include <cuda_runtime.h>
#include <cuda_bf16.h>
#include <cstdint>

// Problem constants (TemporalGNNModel_515396076301)
#define NN 20000
#define EE 640000

typedef unsigned long long ull;

// ---------------- device scratch (static: no allocations allowed) -------------
__device__ int   g_is64;
__device__ int   g_cnt[NN];
__device__ int   g_cursor[NN];
__device__ int   g_rowptr[NN + 1];
__device__ float g_dinv[NN];
__device__ int2  g_edge[EE];         // (src col, norm weight as float bits)
__device__ float g_hbuf[64000000];   // [T,N,H]  x @ gcn_w
__device__ float g_seq[64000000];    // [T,N,H]  GCN output sequence

// ---------------- helpers ----------------------------------------------------
__device__ __forceinline__ int edge_at(const void* e, long long idx) {
    if (g_is64) return (int)((const long long*)e)[idx];
    return ((const int*)e)[idx];
}
__device__ __forceinline__ float sigf(float x) {
    return __fdividef(1.0f, 1.0f + __expf(-x));
}
__device__ __forceinline__ float tanh_fast(float x) {
    return 2.0f * sigf(2.0f * x) - 1.0f;
}
__device__ __forceinline__ uint32_t smem_u32(const void* p) {
    uint32_t a;
    asm("{ .reg .u64 t; cvta.to.shared.u64 t, %1; cvt.u32.u64 %0, t; }"
        : "=r"(a) : "l"(p));
    return a;
}

// ---- packed f32x2 helpers (k_transform) --------------------------------------
__device__ __forceinline__ ull fma2(ull a, ull b, ull c) {
    ull d;
    asm("fma.rn.f32x2 %0, %1, %2, %3;" : "=l"(d) : "l"(a), "l"(b), "l"(c));
    return d;
}
__device__ __forceinline__ ull dup2(float a) {
    ull r; unsigned u = __float_as_uint(a);
    asm("mov.b64 %0, {%1, %1};" : "=l"(r) : "r"(u));
    return r;
}
__device__ __forceinline__ void unpack2(ull v, float& x, float& y) {
    unsigned lo, hi;
    asm("mov.b64 {%0, %1}, %2;" : "=r"(lo), "=r"(hi) : "l"(v));
    x = __uint_as_float(lo); y = __uint_as_float(hi);
}

// ---------------- K0..K4: CSR build ------------------------------------------
__global__ void k_init(const void* e, int N) {
    int i = blockIdx.x * blockDim.x + threadIdx.x;
    if (i < N) { g_cnt[i] = 0; g_cursor[i] = 0; }
    if (i == 0) {
        const unsigned long long* p = (const unsigned long long*)e;
        int is64 = 1;
        for (int k = 0; k < 64; k++)
            if (p[k] >= (unsigned long long)N) { is64 = 0; break; }
        g_is64 = is64;
    }
}
__global__ void k_count(const void* e, int E) {
    int i = blockIdx.x * blockDim.x + threadIdx.x;
    if (i >= E) return;
    atomicAdd(&g_cnt[edge_at(e, (long long)E + i)], 1);
}
__global__ void k_dinv(int N) {
    int i = blockIdx.x * blockDim.x + threadIdx.x;
    if (i >= N) return;
    g_dinv[i] = rsqrtf((float)(g_cnt[i] + 1));
}
__global__ void k_scan(int N) {
    __shared__ int wsum[32];
    int tid = threadIdx.x;
    int chunk = (N + 1023) >> 10;
    int lo = tid * chunk, hi = min(lo + chunk, N);
    int s = 0;
    for (int i = lo; i < hi; i++) s += g_cnt[i];
    int l = tid & 31, w = tid >> 5;
    int inc = s;
#pragma unroll
    for (int o = 1; o < 32; o <<= 1) {
        int v = __shfl_up_sync(0xffffffffu, inc, o);
        if (l >= o) inc += v;
    }
    if (l == 31) wsum[w] = inc;
    __syncthreads();
    if (w == 0) {
        int v = wsum[l], iv = v;
#pragma unroll
        for (int o = 1; o < 32; o <<= 1) {
            int u = __shfl_up_sync(0xffffffffu, iv, o);
            if (l >= o) iv += u;
        }
        wsum[l] = iv - v;
    }
    __syncthreads();
    int run = wsum[w] + (inc - s);
    for (int i = lo; i < hi; i++) { g_rowptr[i] = run; run += g_cnt[i]; }
    if (hi == N) g_rowptr[N] = run;
}
__global__ void k_fill(const void* e, int E) {
    int i = blockIdx.x * blockDim.x + threadIdx.x;
    if (i >= E) return;
    int s = edge_at(e, i);
    int d = edge_at(e, (long long)E + i);
    int slot = g_rowptr[d] + atomicAdd(&g_cursor[d], 1);
    g_edge[slot] = make_int2(s, __float_as_int(g_dinv[s] * g_dinv[d]));
}

// ---------------- K5: transform ------------------------------------------------
__global__ void k_transform(const float* __restrict__ x,
                            const float* __restrict__ W, int R) {
    extern __shared__ float sm[];
    float* Xs = sm;
    float* Ws = sm + 128 * 64;
    int t = threadIdx.x;
    long long r0 = (long long)blockIdx.x * 128;
    for (int i = t; i < 64 * 64; i += 256) Ws[i] = W[i];
    for (int i = t; i < 128 * 16; i += 256) {
        int row = i >> 4, q = i & 15;
        float4 v = make_float4(0.f, 0.f, 0.f, 0.f);
        if (r0 + row < R) v = ((const float4*)x)[(r0 + row) * 16 + q];
        *(float4*)&Xs[row * 64 + q * 4] = v;
    }
    __syncthreads();
    int tx = t & 15, ty = t >> 4;
    ull acc2[8][2];
#pragma unroll
    for (int i = 0; i < 8; i++) { acc2[i][0] = 0; acc2[i][1] = 0; }
#pragma unroll 8
    for (int k = 0; k < 64; k++) {
        const ull* wp = (const ull*)&Ws[k * 64 + tx * 4];
        ull w2a = wp[0], w2b = wp[1];
#pragma unroll
        for (int i = 0; i < 8; i++) {
            ull a2 = dup2(Xs[(ty * 8 + i) * 64 + k]);
            acc2[i][0] = fma2(w2a, a2, acc2[i][0]);
            acc2[i][1] = fma2(w2b, a2, acc2[i][1]);
        }
    }
#pragma unroll
    for (int i = 0; i < 8; i++) {
        long long row = r0 + ty * 8 + i;
        if (row < R) {
            float4 v;
            unpack2(acc2[i][0], v.x, v.y);
            unpack2(acc2[i][1], v.z, v.w);
            *(float4*)&g_hbuf[row * 64 + tx * 4] = v;
        }
    }
}

// ---------------- K6: aggregate ------------------------------------------------
__global__ void k_agg(const float* __restrict__ gcn_b, int N, int nbd) {
    int t = blockIdx.x / nbd;
    int dst = ((blockIdx.x % nbd) << 3) + (threadIdx.x >> 5);
    if (dst >= N) return;
    int l = threadIdx.x & 31;
    const float2* hb = (const float2*)g_hbuf;
    long long tbase = (long long)t * N;
    float dv = g_dinv[dst];
    float2 acc;
    {
        float2 v = hb[(tbase + dst) * 32 + l];
        float sw = dv * dv;
        acc.x = sw * v.x; acc.y = sw * v.y;
    }
    int e = g_rowptr[dst], e1 = g_rowptr[dst + 1];
    for (; e + 4 <= e1; e += 4) {
        int2 p0 = g_edge[e], p1 = g_edge[e + 1], p2 = g_edge[e + 2], p3 = g_edge[e + 3];
        float2 v0 = hb[(tbase + p0.x) * 32 + l];
        float2 v1 = hb[(tbase + p1.x) * 32 + l];
        float2 v2 = hb[(tbase + p2.x) * 32 + l];
        float2 v3 = hb[(tbase + p3.x) * 32 + l];
        acc.x += __int_as_float(p0.y) * v0.x; acc.y += __int_as_float(p0.y) * v0.y;
        acc.x += __int_as_float(p1.y) * v1.x; acc.y += __int_as_float(p1.y) * v1.y;
        acc.x += __int_as_float(p2.y) * v2.x; acc.y += __int_as_float(p2.y) * v2.y;
        acc.x += __int_as_float(p3.y) * v3.x; acc.y += __int_as_float(p3.y) * v3.y;
    }
    for (; e < e1; e++) {
        int2 p = g_edge[e];
        float2 v = hb[(tbase + p.x) * 32 + l];
        acc.x += __int_as_float(p.y) * v.x; acc.y += __int_as_float(p.y) * v.y;
    }
    float2 b2 = ((const float2*)gcn_b)[l];
    float2 r;
    r.x = fmaxf(acc.x + b2.x, 0.f);
    r.y = fmaxf(acc.y + b2.y, 0.f);
    ((float2*)g_seq)[(tbase + dst) * 32 + l] = r;
}

// ---------------- K7: LSTM, mma.sync + ldmatrix + RUNTIME-PROBED D layout ------
// CTA = 80 nodes, 10 warps: wr = w%5 -> rows 16wr..+15; dg = w/5 -> gate cols
// n0 = 128dg..+127 (16 n-tiles of 8). Per step: gates[80,256] = A[80,128] @
// B[128,256], bf16 hi/lo 3-pass split. B col n = 4*dim + gate (pure index
// math). A/B loaded with ldmatrix from UNSWIZZLED padded rows. The D-fragment
// (row, col) per lane slot is DISCOVERED at startup via two probe MMAs, so no
// accumulator-layout knowledge is assumed anywhere. Epilogue round-trips each
// D tile through per-warp scratch: store by probed coords, read canonically.
#define NPC 80
#define THR 320
#define AST 272                            // A row stride bytes
#define BHS 272                            // B-hi row stride bytes
#define BLS 256                            // B-lo row stride bytes (unpadded)
#define OFF_AHI  0                         // 80*272  = 21760
#define OFF_ALO  21760
#define OFF_BHI  43520                     // 256*272 = 69632
#define OFF_BLO  113152                    // 256*256 = 65536
#define OFF_SCR  178688                    // 10 warps * 512B
#define OFF_PRB  183808                    // probe staging: A 512B + B 256B
#define OFF_BIAS 184576                    // 256 f32
#define OFF_OSM  185600                    // 80 f32 (+pad)
#define SMEM_LT  185984

__device__ __forceinline__ void ldsm_x4(uint32_t* r, uint32_t a) {
    asm volatile("ldmatrix.sync.aligned.m8n8.x4.shared.b16 {%0,%1,%2,%3}, [%4];"
                 : "=r"(r[0]), "=r"(r[1]), "=r"(r[2]), "=r"(r[3]) : "r"(a));
}
__device__ __forceinline__ void ldsm_x2(uint32_t* r, uint32_t a) {
    asm volatile("ldmatrix.sync.aligned.m8n8.x2.shared.b16 {%0,%1}, [%2];"
                 : "=r"(r[0]), "=r"(r[1]) : "r"(a));
}
__device__ __forceinline__ void mma16816(float4& d, const uint32_t a[4],
                                         uint32_t b0, uint32_t b1) {
    asm volatile(
        "mma.sync.aligned.m16n8k16.row.col.f32.bf16.bf16.f32 "
        "{%0,%1,%2,%3}, {%4,%5,%6,%7}, {%8,%9}, {%0,%1,%2,%3};"
        : "+f"(d.x), "+f"(d.y), "+f"(d.z), "+f"(d.w)
        : "r"(a[0]), "r"(a[1]), "r"(a[2]), "r"(a[3]), "r"(b0), "r"(b1));
}
__device__ __forceinline__ void pack8(const float* v, uint4& hv, uint4& lv) {
    unsigned h[8], l[8];
#pragma unroll
    for (int i = 0; i < 8; i++) {
        __nv_bfloat16 b = __float2bfloat16_rn(v[i]);
        float rem = v[i] - __bfloat162float(b);
        __nv_bfloat16 c = __float2bfloat16_rn(rem);
        h[i] = (unsigned)__bfloat16_as_ushort(b);
        l[i] = (unsigned)__bfloat16_as_ushort(c);
    }
    hv = make_uint4(h[0] | (h[1] << 16), h[2] | (h[3] << 16),
                    h[4] | (h[5] << 16), h[6] | (h[7] << 16));
    lv = make_uint4(l[0] | (l[1] << 16), l[2] | (l[3] << 16),
                    l[4] | (l[5] << 16), l[6] | (l[7] << 16));
}

__global__ __launch_bounds__(THR, 1)
void k_lstm_pb(const float* __restrict__ w_ih, const float* __restrict__ w_hh,
               const float* __restrict__ b_ih, const float* __restrict__ b_hh,
               const float* __restrict__ fc_w, const float* __restrict__ fc_b,
               float* __restrict__ out, int N, int T) {
    extern __shared__ char smc[];
    uint32_t sb = smem_u32(smc);
    float* scr     = (float*)(smc + OFF_SCR);
    float* bias_sm = (float*)(smc + OFF_BIAS);
    float* osm     = (float*)(smc + OFF_OSM);
    __nv_bfloat16* prb = (__nv_bfloat16*)(smc + OFF_PRB);

    int tid = threadIdx.x;
    int w = tid >> 5, lane = tid & 31;
    int wr = w % 5, dg = w / 5;
    int m0 = wr * 16, n0 = dg * 128;
    int base = blockIdx.x * NPC;

    // ---- B fill: col n = 4*dim + gate; source row r = (n&3)*64 + (n>>2) ----
    for (int i = tid; i < 256 * 128; i += THR) {
        int n = i >> 7, k = i & 127;
        int r = (n & 3) * 64 + (n >> 2);
        float v = (k < 64) ? w_ih[r * 64 + k] : w_hh[r * 64 + (k - 64)];
        __nv_bfloat16 hi = __float2bfloat16_rn(v);
        __nv_bfloat16 lo = __float2bfloat16_rn(v - __bfloat162float(hi));
        *(__nv_bfloat16*)(smc + OFF_BHI + n * BHS + k * 2) = hi;
        *(__nv_bfloat16*)(smc + OFF_BLO + n * BLS + k * 2) = lo;
    }
    if (tid < 256) {
        int r = (tid & 3) * 64 + (tid >> 2);
        bias_sm[tid] = b_ih[r] + b_hh[r];
    }
    if (tid < NPC) osm[tid] = 0.f;

    // ---- initial A: s(0) at k 0..63, h(0)=0 at k 64..127 ----
    int srow = tid >> 2, scg = tid & 3;   // 320 threads = 80 rows x 4 quarters
    {
        float v[16];
        int node = base + srow;
        if (node < N) {
            const float4* sp = (const float4*)(g_seq + (long long)node * 64 + scg * 16);
#pragma unroll
            for (int j = 0; j < 4; j++) *(float4*)&v[j * 4] = sp[j];
        } else {
#pragma unroll
            for (int j = 0; j < 16; j++) v[j] = 0.f;
        }
        uint4 hv, lv;
        int b0 = srow * AST + scg * 32;
        pack8(v, hv, lv);
        *(uint4*)(smc + OFF_AHI + b0)      = hv;  *(uint4*)(smc + OFF_ALO + b0)      = lv;
        pack8(v + 8, hv, lv);
        *(uint4*)(smc + OFF_AHI + b0 + 16) = hv;  *(uint4*)(smc + OFF_ALO + b0 + 16) = lv;
        uint4 z = make_uint4(0, 0, 0, 0);
        int b1 = srow * AST + 128 + scg * 32;
        *(uint4*)(smc + OFF_AHI + b1)      = z;   *(uint4*)(smc + OFF_ALO + b1)      = z;
        *(uint4*)(smc + OFF_AHI + b1 + 16) = z;   *(uint4*)(smc + OFF_ALO + b1 + 16) = z;
    }

    // ---- PROBE: discover D-fragment (row, col) per lane slot ----
    int rowIdx[4], colIdx[4];
    {
        uint32_t aaddr = sb + OFF_PRB + (lane & 15) * 32 + (lane >> 4) * 16;
        uint32_t baddr = sb + OFF_PRB + 512 + (lane & 7) * 32 + ((lane >> 3) & 1) * 16;
        float4 P;
        uint32_t a[4], b[2];
        // probe 1: A[r][0] = r, B[0][c] = 1  ->  D[r][c] = r
        for (int i = tid; i < 256; i += THR) {
            int r = i >> 4, k = i & 15;
            prb[r * 16 + k] = __float2bfloat16_rn((k == 0) ? (float)r : 0.f);
        }
        for (int i = tid; i < 128; i += THR) {
            int n = i >> 4, k = i & 15;
            prb[256 + n * 16 + k] = __float2bfloat16_rn((k == 0) ? 1.f : 0.f);
        }
        __syncthreads();
        P = make_float4(0.f, 0.f, 0.f, 0.f);
        ldsm_x4(a, aaddr); ldsm_x2(b, baddr);
        mma16816(P, a, b[0], b[1]);
        rowIdx[0] = (int)(P.x + 0.5f); rowIdx[1] = (int)(P.y + 0.5f);
        rowIdx[2] = (int)(P.z + 0.5f); rowIdx[3] = (int)(P.w + 0.5f);
        __syncthreads();
        // probe 2: A[r][0] = 1, B[0][c] = c  ->  D[r][c] = c
        for (int i = tid; i < 256; i += THR) {
            int r = i >> 4, k = i & 15;
            prb[r * 16 + k] = __float2bfloat16_rn((k == 0) ? 1.f : 0.f);
        }
        for (int i = tid; i < 128; i += THR) {
            int n = i >> 4, k = i & 15;
            prb[256 + n * 16 + k] = __float2bfloat16_rn((k == 0) ? (float)n : 0.f);
        }
        __syncthreads();
        P = make_float4(0.f, 0.f, 0.f, 0.f);
        ldsm_x4(a, aaddr); ldsm_x2(b, baddr);
        mma16816(P, a, b[0], b[1]);
        colIdx[0] = (int)(P.x + 0.5f); colIdx[1] = (int)(P.y + 0.5f);
        colIdx[2] = (int)(P.z + 0.5f); colIdx[3] = (int)(P.w + 0.5f);
    }
    // clamp into scratch bounds (garbage-safe: wrong answer, never corruption)
    int sidx[4];
#pragma unroll
    for (int s = 0; s < 4; s++)
        sidx[s] = ((rowIdx[s] & 15) * 8 + (colIdx[s] & 7));

    // ---- per-lane addresses (ldmatrix; standard lane->row grouping) ----
    uint32_t aOff = (uint32_t)(m0 + (lane & 15)) * AST + (lane >> 4) * 16;
    int bRow = n0 + 8 * ((lane >> 4) & 1) + (lane & 7);
    uint32_t kg16 = ((lane >> 3) & 1) * 16;

    float* scr_w = scr + w * 128;          // 16x8 f32 tile
    int erow = lane >> 1, dsel = lane & 1; // epilogue: cell (erow, 2nt+dsel)
    float cst[16];
#pragma unroll
    for (int i = 0; i < 16; i++) cst[i] = 0.f;
    float fcs = 0.f;

#pragma unroll 1
    for (int t = 0; t < T; t++) {
        float pf[16];
        bool hp = (t + 1) < T;
        if (hp) {
            int node = base + srow;
            if (node < N) {
                const float4* sp = (const float4*)(g_seq +
                    ((long long)(t + 1) * N + node) * 64 + scg * 16);
#pragma unroll
                for (int j = 0; j < 4; j++) *(float4*)&pf[j * 4] = sp[j];
            } else {
#pragma unroll
                for (int j = 0; j < 16; j++) pf[j] = 0.f;
            }
        }

        __syncthreads();                   // A writes from prev step visible

        float4 D[16];
#pragma unroll
        for (int q = 0; q < 16; q++) D[q] = make_float4(0.f, 0.f, 0.f, 0.f);

#pragma unroll 1
        for (int ps = 0; ps < 3; ps++) {
            uint32_t Ab = sb + ((ps == 2) ? OFF_ALO : OFF_AHI);
            int bLo = (ps == 1);
#pragma unroll 1
            for (int kc = 0; kc < 8; kc++) {
                uint32_t kb = kc * 32;
                uint32_t a[4];
                ldsm_x4(a, Ab + aOff + kb);
#pragma unroll
                for (int p = 0; p < 8; p++) {
                    uint32_t bb[4];
                    uint32_t ba = bLo
                        ? sb + OFF_BLO + (uint32_t)(bRow + 16 * p) * BLS + kb + kg16
                        : sb + OFF_BHI + (uint32_t)(bRow + 16 * p) * BHS + kb + kg16;
                    ldsm_x4(bb, ba);
                    mma16816(D[2 * p],     a, bb[0], bb[1]);
                    mma16816(D[2 * p + 1], a, bb[2], bb[3]);
                }
            }
        }

        __syncthreads();                   // all A reads done before h writes

        // ---- epilogue: per n-tile scratch round-trip via probed coords ----
#pragma unroll 1
        for (int nt = 0; nt < 16; nt++) {
            scr_w[sidx[0]] = D[nt].x;
            scr_w[sidx[1]] = D[nt].y;
            scr_w[sidx[2]] = D[nt].z;
            scr_w[sidx[3]] = D[nt].w;
            __syncwarp();
            int nb = n0 + 8 * nt;
            float iv = scr_w[erow * 8 + dsel * 4 + 0] + bias_sm[nb + dsel * 4 + 0];
            float fv = scr_w[erow * 8 + dsel * 4 + 1] + bias_sm[nb + dsel * 4 + 1];
            float gv = scr_w[erow * 8 + dsel * 4 + 2] + bias_sm[nb + dsel * 4 + 2];
            float ov = scr_w[erow * 8 + dsel * 4 + 3] + bias_sm[nb + dsel * 4 + 3];
            float c = sigf(fv) * cst[nt] + sigf(iv) * tanh_fast(gv);
            cst[nt] = c;
            float h = sigf(ov) * tanh_fast(c);
            int dim = (nb >> 2) + dsel;
            int grow = m0 + erow;
            int el = grow * AST + (64 + dim) * 2;
            __nv_bfloat16 bh = __float2bfloat16_rn(h);
            *(__nv_bfloat16*)(smc + OFF_AHI + el) = bh;
            *(__nv_bfloat16*)(smc + OFF_ALO + el) =
                __float2bfloat16_rn(h - __bfloat162float(bh));
            if (t == T - 1) fcs += h * __ldg(&fc_w[dim]);
            __syncwarp();
        }

        if (hp) {
            uint4 hv, lv;
            int b0 = srow * AST + scg * 32;
            pack8(pf, hv, lv);
            *(uint4*)(smc + OFF_AHI + b0)      = hv;  *(uint4*)(smc + OFF_ALO + b0)      = lv;
            pack8(pf + 8, hv, lv);
            *(uint4*)(smc + OFF_AHI + b0 + 16) = hv;  *(uint4*)(smc + OFF_ALO + b0 + 16) = lv;
        }
    }

    // FC: combine dim pair, then the two dim-half warps via osm atomics
    fcs += __shfl_xor_sync(0xffffffffu, fcs, 1);
    if (dsel == 0) atomicAdd(&osm[m0 + erow], fcs);

    __syncthreads();
    if (tid < NPC && base + tid < N) out[base + tid] = osm[tid] + fc_b[0];
}

// ---------------- launcher ------------------------------------------------------
extern "C" void kernel_launch(void* const* d_in, const int* in_sizes, int n_in,
                              void* d_out, int out_size) {
    const float* x     = (const float*)d_in[0];
    const void*  edges = d_in[1];
    const float* gcn_w = (const float*)d_in[2];
    const float* gcn_b = (const float*)d_in[3];
    const float* w_ih  = (const float*)d_in[4];
    const float* w_hh  = (const float*)d_in[5];
    const float* b_ih  = (const float*)d_in[6];
    const float* b_hh  = (const float*)d_in[7];
    const float* fc_w  = (const float*)d_in[8];
    const float* fc_b  = (const float*)d_in[9];
    float* out = (float*)d_out;

    int N = out_size;                 // 20000
    int E = in_sizes[1] / 2;          // 640000
    int H = in_sizes[3];              // 64
    int F = in_sizes[2] / H;          // 64
    int T = in_sizes[0] / (N * F);    // 50
    int R = T * N;

    cudaFuncSetAttribute(k_lstm_pb, cudaFuncAttributeMaxDynamicSharedMemorySize,
                         SMEM_LT);

    k_init <<<(N + 255) / 256, 256>>>(edges, N);
    k_count<<<(E + 255) / 256, 256>>>(edges, E);
    k_dinv <<<(N + 255) / 256, 256>>>(N);
    k_scan <<<1, 1024>>>(N);
    k_fill <<<(E + 255) / 256, 256>>>(edges, E);

    k_transform<<<(R + 127) / 128, 256, (128 * 64 + 64 * 64) * 4>>>(x, gcn_w, R);

    int nbd = (N + 7) >> 3;
    k_agg<<<T * nbd, 256>>>(gcn_b, N, nbd);

    k_lstm_pb<<<(N + NPC - 1) / NPC, THR, SMEM_LT>>>(
        w_ih, w_hh, b_ih, b_hh, fc_w, fc_b, out, N, T);
}